// round 1
// baseline (speedup 1.0000x reference)
#include <cuda_runtime.h>
#include <math.h>

#define NA 20000
#define NE 320000
#define F 128
#define F3 (3*F)
#define NRBF 20
#define NCONV 3
#define CUTOFF 5.0f
#define PI_F 3.14159265358979323846f

// ---------------- scratch (device globals; no allocation allowed) ----------------
__device__ float g_s[NA * F];
__device__ float g_v[NA * F3];      // layout (n, d, f): v[n*384 + d*128 + f]
__device__ float g_t[NA * F];       // generic 128-wide temp
__device__ float g_phi[NA * F3];    // phi / also reused as h in readout
__device__ float g_ds[NA * F];
__device__ float g_dv[NA * F3];
__device__ float g_uv[NA * F3];
__device__ float g_vv[NA * F3];
__device__ float g_cat[NA * 2 * F];
__device__ float g_split[NA * F3];
__device__ float g_unit[NE * 3];
__device__ float g_fcut[NE];
__device__ float g_rbf[NE * NRBF];
__device__ float g_fea[NA * 64];

__device__ __forceinline__ float silu_f(float x) { return x / (1.0f + expf(-x)); }

// ---------------- edge geometry (once) ----------------
__global__ void edge_geom_kernel(const float* __restrict__ xyz,
                                 const int* __restrict__ nbrs) {
    int e = blockIdx.x * blockDim.x + threadIdx.x;
    if (e >= NE) return;
    int i = nbrs[2 * e], j = nbrs[2 * e + 1];
    float dx = xyz[3 * j + 0] - xyz[3 * i + 0];
    float dy = xyz[3 * j + 1] - xyz[3 * i + 1];
    float dz = xyz[3 * j + 2] - xyz[3 * i + 2];
    float d = sqrtf(dx * dx + dy * dy + dz * dz + 1e-12f);
    float inv = 1.0f / d;
    g_unit[3 * e + 0] = dx * inv;
    g_unit[3 * e + 1] = dy * inv;
    g_unit[3 * e + 2] = dz * inv;
    g_fcut[e] = (d < CUTOFF) ? 0.5f * (cosf(PI_F * d / CUTOFF) + 1.0f) : 0.0f;
    float a = PI_F * d / CUTOFF;
#pragma unroll
    for (int k = 0; k < NRBF; k++)
        g_rbf[e * NRBF + k] = sinf((float)(k + 1) * a) * inv;
}

// ---------------- init: s = embed[z], v = 0 ----------------
__global__ void embed_init_kernel(const int* __restrict__ z,
                                  const float* __restrict__ embed) {
    int t = blockIdx.x * blockDim.x + threadIdx.x;
    if (t < NA * F) {
        int n = t / F, f = t % F;
        g_s[t] = embed[z[n] * F + f];
    }
    if (t < NA * F3) g_v[t] = 0.0f;
}

// ---------------- fused edge message kernel ----------------
// thread t (0..127) owns feature t in each of the 3 chunks of inv.
// blockDim = (128, 2): 2 edges per block iteration.
__global__ void edge_msg_kernel(const int* __restrict__ nbrs,
                                const float* __restrict__ Wd,
                                const float* __restrict__ bd) {
    __shared__ float sWd[NRBF * F3];
    __shared__ float sbd[F3];
    int tid = threadIdx.y * blockDim.x + threadIdx.x;
    for (int idx = tid; idx < NRBF * F3; idx += 256) sWd[idx] = Wd[idx];
    for (int idx = tid; idx < F3; idx += 256) sbd[idx] = bd[idx];
    __syncthreads();

    int t = threadIdx.x;
    for (int e = blockIdx.x * 2 + threadIdx.y; e < NE; e += gridDim.x * 2) {
        float fc = g_fcut[e];
        if (fc == 0.0f) continue;  // whole contribution is zero
        int i = nbrs[2 * e], j = nbrs[2 * e + 1];
        float r[NRBF];
#pragma unroll
        for (int k = 0; k < NRBF; k++) r[k] = g_rbf[e * NRBF + k];

        float w0 = sbd[t], w1 = sbd[F + t], w2 = sbd[2 * F + t];
#pragma unroll
        for (int k = 0; k < NRBF; k++) {
            float rk = r[k];
            w0 += rk * sWd[k * F3 + t];
            w1 += rk * sWd[k * F3 + F + t];
            w2 += rk * sWd[k * F3 + 2 * F + t];
        }
        w0 *= fc; w1 *= fc; w2 *= fc;

        float inv0 = g_phi[j * F3 + t]         * w0;
        float inv1 = g_phi[j * F3 + F + t]     * w1;
        float inv2 = g_phi[j * F3 + 2 * F + t] * w2;

        float ux = g_unit[3 * e + 0];
        float uy = g_unit[3 * e + 1];
        float uz = g_unit[3 * e + 2];
        float vj0 = g_v[j * F3 + t];
        float vj1 = g_v[j * F3 + F + t];
        float vj2 = g_v[j * F3 + 2 * F + t];

        atomicAdd(&g_ds[i * F + t], inv1);
        atomicAdd(&g_dv[i * F3 + t],         ux * inv2 + inv0 * vj0);
        atomicAdd(&g_dv[i * F3 + F + t],     uy * inv2 + inv0 * vj1);
        atomicAdd(&g_dv[i * F3 + 2 * F + t], uz * inv2 + inv0 * vj2);
    }
}

// ---------------- apply deltas then clear (keeps graph replays deterministic) ----
__global__ void apply_clear_kernel() {
    int t = blockIdx.x * blockDim.x + threadIdx.x;
    if (t < NA * F) {
        g_s[t] += g_ds[t];
        g_ds[t] = 0.0f;
    } else if (t < NA * F + NA * F3) {
        int u = t - NA * F;
        g_v[u] += g_dv[u];
        g_dv[u] = 0.0f;
    }
}

// ---------------- vnorm + concat ----------------
__global__ void vnorm_cat_kernel() {
    int t = blockIdx.x * blockDim.x + threadIdx.x;
    if (t >= NA * F) return;
    int n = t / F, f = t % F;
    g_cat[n * 2 * F + f] = g_s[t];
    float a = g_vv[n * F3 + f];
    float b = g_vv[n * F3 + F + f];
    float c = g_vv[n * F3 + 2 * F + f];
    g_cat[n * 2 * F + F + f] = sqrtf(a * a + b * b + c * c + 1e-12f);
}

// ---------------- gated update ----------------
__global__ void update_kernel() {
    int t = blockIdx.x * blockDim.x + threadIdx.x;
    if (t >= NA * F) return;
    int n = t / F, f = t % F;
    float avv = g_split[n * F3 + f];
    float asv = g_split[n * F3 + F + f];
    float ass = g_split[n * F3 + 2 * F + f];
    float dot = 0.0f;
#pragma unroll
    for (int d = 0; d < 3; d++) {
        float u = g_uv[n * F3 + d * F + f];
        float w = g_vv[n * F3 + d * F + f];
        dot += u * w;
        g_v[n * F3 + d * F + f] += u * avv;
    }
    g_s[t] += dot * asv + ass;
}

// ---------------- generic tiled GEMM: C = act(A[M,K] @ W[K,N] + b) ------------
// BM=128, BN=64, BK=16, 256 threads, 8x4 per thread. ACT: 0 none, 1 silu.
template <int ACT>
__global__ void __launch_bounds__(256)
gemm_kernel(const float* __restrict__ A, const float* __restrict__ W,
            const float* __restrict__ bias, float* __restrict__ C,
            int M, int N, int K) {
    const int BM = 128, BN = 64, BK = 16;
    __shared__ float As[BK][BM];
    __shared__ float Bs[BK][BN];
    int tid = threadIdx.x;
    int tx = tid % 16, ty = tid / 16;
    int m0 = blockIdx.y * BM, n0 = blockIdx.x * BN;

    float acc[8][4] = {};
    int am = tid / 2;          // 0..127
    int ak = (tid & 1) * 8;    // 0 or 8
    int bn = tid % 64;
    int bk0 = tid / 64;        // 0..3

    for (int k0 = 0; k0 < K; k0 += BK) {
#pragma unroll
        for (int i = 0; i < 8; i++) {
            int k = ak + i;
            int gm = m0 + am, gk = k0 + k;
            As[k][am] = (gm < M && gk < K) ? A[gm * K + gk] : 0.0f;
        }
#pragma unroll
        for (int i = 0; i < 4; i++) {
            int k = bk0 + i * 4;
            int gk = k0 + k, gn = n0 + bn;
            Bs[k][bn] = (gk < K && gn < N) ? W[gk * N + gn] : 0.0f;
        }
        __syncthreads();
#pragma unroll
        for (int kk = 0; kk < BK; kk++) {
            float ra[8], rb[4];
#pragma unroll
            for (int r = 0; r < 8; r++) ra[r] = As[kk][ty * 8 + r];
#pragma unroll
            for (int c = 0; c < 4; c++) rb[c] = Bs[kk][tx * 4 + c];
#pragma unroll
            for (int r = 0; r < 8; r++)
#pragma unroll
                for (int c = 0; c < 4; c++) acc[r][c] += ra[r] * rb[c];
        }
        __syncthreads();
    }
#pragma unroll
    for (int r = 0; r < 8; r++) {
        int row = m0 + ty * 8 + r;
        if (row >= M) continue;
#pragma unroll
        for (int c = 0; c < 4; c++) {
            int col = n0 + tx * 4 + c;
            if (col >= N) continue;
            float x = acc[r][c] + (bias ? bias[col] : 0.0f);
            if (ACT == 1) x = silu_f(x);
            C[row * N + col] = x;
        }
    }
}

// ---------------- final projection N=5 (warp per atom) ----------------
__global__ void out_kernel(const float* __restrict__ Wf3,
                           const float* __restrict__ bf3,
                           float* __restrict__ out) {
    int gw = (blockIdx.x * blockDim.x + threadIdx.x) >> 5;
    int lane = threadIdx.x & 31;
    if (gw >= NA) return;
    float acc[5] = {0.f, 0.f, 0.f, 0.f, 0.f};
    for (int k = lane; k < F; k += 32) {
        float h = g_t[gw * F + k];
#pragma unroll
        for (int o = 0; o < 5; o++) acc[o] += h * Wf3[k * 5 + o];
    }
#pragma unroll
    for (int o = 0; o < 5; o++) {
#pragma unroll
        for (int off = 16; off > 0; off >>= 1)
            acc[o] += __shfl_xor_sync(0xffffffffu, acc[o], off);
    }
    if (lane == 0) {
#pragma unroll
        for (int o = 0; o < 5; o++) out[gw * 5 + o] = acc[o] + bf3[o];
    }
}

// ---------------- host driver ----------------
static float* sym_addr(const void* symbol) {
    void* p = nullptr;
    cudaGetSymbolAddress(&p, symbol);
    return (float*)p;
}

extern "C" void kernel_launch(void* const* d_in, const int* in_sizes, int n_in,
                              void* d_out, int out_size) {
    const float* xyz   = (const float*)d_in[0];
    const int*   z     = (const int*)d_in[1];
    const int*   nbrs  = (const int*)d_in[2];
    const float* embed = (const float*)d_in[3];
    const float* W1  = (const float*)d_in[4];
    const float* b1  = (const float*)d_in[5];
    const float* W2  = (const float*)d_in[6];
    const float* b2  = (const float*)d_in[7];
    const float* Wd  = (const float*)d_in[8];
    const float* bd  = (const float*)d_in[9];
    const float* U   = (const float*)d_in[10];
    const float* V   = (const float*)d_in[11];
    const float* Ws1 = (const float*)d_in[12];
    const float* bs1 = (const float*)d_in[13];
    const float* Ws2 = (const float*)d_in[14];
    const float* bs2 = (const float*)d_in[15];
    const float* Wr1 = (const float*)d_in[16];
    const float* br1 = (const float*)d_in[17];
    const float* Wr2 = (const float*)d_in[18];
    const float* br2 = (const float*)d_in[19];
    const float* Wf1 = (const float*)d_in[20];
    const float* bf1 = (const float*)d_in[21];
    const float* Wf2 = (const float*)d_in[22];
    const float* bf2 = (const float*)d_in[23];
    const float* Wf3 = (const float*)d_in[24];
    const float* bf3 = (const float*)d_in[25];
    float* out = (float*)d_out;

    float* s     = sym_addr(g_s);
    float* v     = sym_addr(g_v);
    float* t     = sym_addr(g_t);
    float* phi   = sym_addr(g_phi);
    float* uv    = sym_addr(g_uv);
    float* vv    = sym_addr(g_vv);
    float* cat   = sym_addr(g_cat);
    float* split = sym_addr(g_split);
    float* fea   = sym_addr(g_fea);

    const int TPB = 256;
    dim3 gM157_n128(2, 157);   // M=20000, N=128
    dim3 gM157_n384(6, 157);   // M=20000, N=384
    dim3 gM157_n64(1, 157);    // M=20000, N=64
    dim3 gM469_n128(2, 469);   // M=60000, N=128

    edge_geom_kernel<<<(NE + TPB - 1) / TPB, TPB>>>(xyz, nbrs);
    embed_init_kernel<<<(NA * F3 + TPB - 1) / TPB, TPB>>>(z, embed);

    for (int l = 0; l < NCONV; l++) {
        // phi = silu(s@W1+b1) @ W2 + b2
        gemm_kernel<1><<<gM157_n128, 256>>>(s, W1 + l * F * F, b1 + l * F, t, NA, F, F);
        gemm_kernel<0><<<gM157_n384, 256>>>(t, W2 + l * F * F3, b2 + l * F3, phi, NA, F3, F);

        // edge messages -> ds/dv (atomics)
        edge_msg_kernel<<<592, dim3(128, 2)>>>(nbrs, Wd + l * NRBF * F3, bd + l * F3);
        apply_clear_kernel<<<(NA * 4 * F + TPB - 1) / TPB, TPB>>>();

        // u_v = v @ U, v_v = v @ V   (rows = (n,d))
        gemm_kernel<0><<<gM469_n128, 256>>>(v, U + l * F * F, nullptr, uv, NA * 3, F, F);
        gemm_kernel<0><<<gM469_n128, 256>>>(v, V + l * F * F, nullptr, vv, NA * 3, F, F);

        vnorm_cat_kernel<<<(NA * F + TPB - 1) / TPB, TPB>>>();

        // split = silu(cat@Ws1+bs1) @ Ws2 + bs2
        gemm_kernel<1><<<gM157_n128, 256>>>(cat, Ws1 + l * 2 * F * F, bs1 + l * F, t, NA, F, 2 * F);
        gemm_kernel<0><<<gM157_n384, 256>>>(t, Ws2 + l * F * F3, bs2 + l * F3, split, NA, F3, F);

        update_kernel<<<(NA * F + TPB - 1) / TPB, TPB>>>();
    }

    // readout
    gemm_kernel<1><<<gM157_n128, 256>>>(s, Wr1, br1, t, NA, F, F);
    gemm_kernel<0><<<gM157_n64, 256>>>(t, Wr2, br2, fea, NA, 64, F);
    gemm_kernel<1><<<gM157_n128, 256>>>(fea, Wf1, bf1, phi, NA, F, 64);
    gemm_kernel<1><<<gM157_n128, 256>>>(phi, Wf2, bf2, t, NA, F, F);
    out_kernel<<<(NA * 32 + TPB - 1) / TPB, TPB>>>(Wf3, bf3, out);
}